// round 11
// baseline (speedup 1.0000x reference)
#include <cuda_runtime.h>
#include <cuda_bf16.h>
#include <cstdint>

constexpr int BB = 16, NN = 2048, DD = 64;
constexpr int TM = 128, TN = 128;
constexpr int THREADS = 256;          // 8 warps; warp w owns rows 16w..16w+15
constexpr int NT = NN / TN;           // 16 K-tiles
constexpr int KW = 36;                // K smem row stride in 4B words (72 bf16)

__device__ __forceinline__ uint32_t packbf(float x, float y) {
    __nv_bfloat162 h = __floats2bfloat162_rn(x, y);   // lo=x, hi=y
    return *reinterpret_cast<uint32_t*>(&h);
}

__device__ __forceinline__ void mma16816(float* c, const uint32_t* a,
                                         uint32_t b0, uint32_t b1) {
    asm volatile(
        "mma.sync.aligned.m16n8k16.row.col.f32.bf16.bf16.f32 "
        "{%0,%1,%2,%3}, {%4,%5,%6,%7}, {%8,%9}, {%0,%1,%2,%3};"
        : "+f"(c[0]), "+f"(c[1]), "+f"(c[2]), "+f"(c[3])
        : "r"(a[0]), "r"(a[1]), "r"(a[2]), "r"(a[3]), "r"(b0), "r"(b1));
}

__device__ __forceinline__ void ldsm_x4(uint32_t& f0, uint32_t& f1,
                                        uint32_t& f2, uint32_t& f3, uint32_t addr) {
    asm volatile("ldmatrix.sync.aligned.m8n8.x4.shared.b16 {%0,%1,%2,%3}, [%4];"
                 : "=r"(f0), "=r"(f1), "=r"(f2), "=r"(f3) : "r"(addr));
}

constexpr unsigned NEGINF_BITS = 0xFF800000u;

// tile-local top-2 insert of packed (score|col); masked -> -inf falls through
__device__ __forceinline__ void ins2(float& A, float& B, float s, unsigned m, int col) {
    float pf = __int_as_float((__float_as_int(s) & 0xFFFFF800) | col);
    pf = m ? __int_as_float(NEGINF_BITS) : pf;
    float t = fminf(A, pf);
    A = fmaxf(A, pf);
    B = fmaxf(B, t);
}

// global top-4 insert of an already-packed value
__device__ __forceinline__ void ins4(float (&P)[4], float v) {
    float t1 = fminf(P[0], v); P[0] = fmaxf(P[0], v);
    float t2 = fminf(P[1], t1); P[1] = fmaxf(P[1], t1);
    float t3 = fminf(P[2], t2); P[2] = fmaxf(P[2], t2);
    P[3] = fmaxf(P[3], t3);
}

__global__ void __launch_bounds__(THREADS, 2)
attn_fused_kernel(const float* __restrict__ q, const float* __restrict__ kmat,
                  const float* __restrict__ v, const int* __restrict__ maski,
                  float* __restrict__ attn, float* __restrict__ outp)
{
    __shared__ __align__(16) uint32_t Ksm[TN * KW];   // bf16 K tile, 18 KB
    __shared__ uint4 smW[8 * 16];                     // per-warp mask bit-words, 2 KB

    const int tid  = threadIdx.x;
    const int warp = tid >> 5;
    const int lane = tid & 31;
    const int g    = lane >> 2;       // 0..7
    const int tig  = lane & 3;        // 0..3
    const int b       = blockIdx.y;
    const int rowBase = blockIdx.x * TM;
    const int r0 = rowBase + warp * 16 + g;
    const int r1 = r0 + 8;
    const int shb = tig >> 1;         // bit offset base

    uint32_t sKsm;
    asm("{ .reg .u64 t; cvta.to.shared.u64 t, %1; cvt.u32.u64 %0, t; }"
        : "=r"(sKsm) : "l"(Ksm));
    const int lm_m  = lane >> 3;
    const int lm_r  = lane & 7;
    const uint32_t lmBase = sKsm + 4u * ((uint32_t)(8 * (lm_m >> 1) + lm_r) * KW
                                         + (uint32_t)(lm_m & 1) * 4u);

    // ---- A fragments (Q rows r0,r1 as bf16), loaded once ----
    uint32_t aF[4][4];
    {
        const float* q0 = q + ((size_t)b * NN + r0) * DD;
        const float* q1 = q + ((size_t)b * NN + r1) * DD;
        #pragma unroll
        for (int s = 0; s < 4; ++s) {
            float2 x0 = *reinterpret_cast<const float2*>(q0 + 16 * s + 2 * tig);
            float2 x1 = *reinterpret_cast<const float2*>(q1 + 16 * s + 2 * tig);
            float2 x2 = *reinterpret_cast<const float2*>(q0 + 16 * s + 2 * tig + 8);
            float2 x3 = *reinterpret_cast<const float2*>(q1 + 16 * s + 2 * tig + 8);
            aF[s][0] = packbf(x0.x, x0.y);
            aF[s][1] = packbf(x1.x, x1.y);
            aF[s][2] = packbf(x2.x, x2.y);
            aF[s][3] = packbf(x3.x, x3.y);
        }
    }

    const float NEGINF = __int_as_float(NEGINF_BITS);
    float p0[4] = {NEGINF, NEGINF, NEGINF, NEGINF};
    float p1[4] = {NEGINF, NEGINF, NEGINF, NEGINF};

    // mask rows for this warp, int4 view (512 int4 per row)
    const int4* mwarp = reinterpret_cast<const int4*>(
        maski + ((size_t)b * NN + rowBase + warp * 16) * NN);

    for (int t = 0; t < NT; ++t) {
        if (t) __syncthreads();       // prior tile fully consumed

        // ---- K tile load (row = tid>>1, half = (tid&1)*32 dims) + pack ----
        uint4 kp[4];
        {
            const float4* src = reinterpret_cast<const float4*>(
                kmat + ((size_t)b * NN + t * TN + (tid >> 1)) * DD) + (tid & 1) * 8;
            float4 f[8];
            #pragma unroll
            for (int i = 0; i < 8; ++i) f[i] = src[i];
            #pragma unroll
            for (int qt = 0; qt < 4; ++qt)
                kp[qt] = make_uint4(packbf(f[2*qt].x,   f[2*qt].y),
                                    packbf(f[2*qt].z,   f[2*qt].w),
                                    packbf(f[2*qt+1].x, f[2*qt+1].y),
                                    packbf(f[2*qt+1].z, f[2*qt+1].w));
        }

        // ---- mask: ballot-pack this warp's 16 rows x 128 cols ----
        #pragma unroll
        for (int grp = 0; grp < 2; ++grp) {
            int4 mm[8];
            #pragma unroll
            for (int r = 0; r < 8; ++r)
                mm[r] = __ldcs(&mwarp[(size_t)(grp * 8 + r) * (NN / 4) + t * 32 + lane]);
            #pragma unroll
            for (int r = 0; r < 8; ++r) {
                uint32_t b0 = __ballot_sync(0xffffffffu, mm[r].x != 0);
                uint32_t b1 = __ballot_sync(0xffffffffu, mm[r].y != 0);
                uint32_t b2 = __ballot_sync(0xffffffffu, mm[r].z != 0);
                uint32_t b3 = __ballot_sync(0xffffffffu, mm[r].w != 0);
                if (lane == grp * 8 + r)
                    smW[warp * 16 + lane] = make_uint4(b0, b1, b2, b3);
            }
        }

        // ---- K STS ----
        {
            uint32_t* dst = Ksm + (tid >> 1) * KW + (tid & 1) * 16;
            *reinterpret_cast<uint4*>(dst)      = kp[0];
            *reinterpret_cast<uint4*>(dst + 4)  = kp[1];
            *reinterpret_cast<uint4*>(dst + 8)  = kp[2];
            *reinterpret_cast<uint4*>(dst + 12) = kp[3];
        }
        __syncthreads();

        // ---- attn zero slice (independent; drains during compute) ----
        {
            const int zr   = tid >> 1;
            const int half = tid & 1;
            float4* dst = reinterpret_cast<float4*>(
                attn + ((size_t)b * NN + rowBase + zr) * NN + t * TN + half * 64);
            const float4 z = make_float4(0.f, 0.f, 0.f, 0.f);
            #pragma unroll
            for (int j = 0; j < 16; ++j) __stcs(dst + j, z);
        }

        // ---- mask words for my rows ----
        const uint4 W0 = smW[warp * 16 + g];
        const uint4 W1 = smW[warp * 16 + 8 + g];
        const uint32_t wa0 = (tig & 1) ? W0.z : W0.x;
        const uint32_t wb0 = (tig & 1) ? W0.w : W0.y;
        const uint32_t wa1 = (tig & 1) ? W1.z : W1.x;
        const uint32_t wb1 = (tig & 1) ? W1.w : W1.y;

        // ---- tile-local top-2 accumulators (packed), per row ----
        float A0 = NEGINF, B0 = NEGINF, A1 = NEGINF, B1 = NEGINF;
        const int colBase = t * TN;

        #pragma unroll
        for (int jp = 0; jp < 8; ++jp) {
            float c2[2][4];
            #pragma unroll
            for (int u = 0; u < 2; ++u)
                #pragma unroll
                for (int e = 0; e < 4; ++e) c2[u][e] = 0.f;

            const uint32_t aj = lmBase + 4u * (uint32_t)((16 * jp) * KW);
            #pragma unroll
            for (int s = 0; s < 4; ++s) {
                uint32_t f0, f1, f2, f3;
                ldsm_x4(f0, f1, f2, f3, aj + 32u * s);
                mma16816(c2[0], aF[s], f0, f1);
                mma16816(c2[1], aF[s], f2, f3);
            }

            const int sh0 = 4 * jp + shb;       // mma j = 2jp
            const int sh1 = sh0 + 2;            // mma j = 2jp+1
            const int col0 = colBase + 16 * jp + 2 * tig;
            ins2(A0, B0, c2[0][0], (wa0 >> sh0) & 1u, col0);
            ins2(A0, B0, c2[0][1], (wb0 >> sh0) & 1u, col0 + 1);
            ins2(A1, B1, c2[0][2], (wa1 >> sh0) & 1u, col0);
            ins2(A1, B1, c2[0][3], (wb1 >> sh0) & 1u, col0 + 1);
            ins2(A0, B0, c2[1][0], (wa0 >> sh1) & 1u, col0 + 8);
            ins2(A0, B0, c2[1][1], (wb0 >> sh1) & 1u, col0 + 9);
            ins2(A1, B1, c2[1][2], (wa1 >> sh1) & 1u, col0 + 8);
            ins2(A1, B1, c2[1][3], (wb1 >> sh1) & 1u, col0 + 9);
        }

        // ---- merge tile top-2 into global top-4 ----
        ins4(p0, A0); ins4(p0, B0);
        ins4(p1, A1); ins4(p1, B1);
    }

    // ---- exact fp32 rescore of <=4 candidates/lane (round-2-verified order) ----
    __syncthreads();   // all zero-stores done & visible before scatter
    auto finish = [&](float (&P)[4], int row) {
        float bE = -__int_as_float(0x7f800000);
        int   bI = 0x7fffffff;
        #pragma unroll
        for (int i = 0; i < 4; ++i) {
            if (P[i] != NEGINF) {
                const int cI = __float_as_int(P[i]) & 0x7FF;
                const float4* qr = reinterpret_cast<const float4*>(q + ((size_t)b * NN + row) * DD);
                const float4* kr = reinterpret_cast<const float4*>(kmat + ((size_t)b * NN + cI) * DD);
                float acc = 0.f;
                #pragma unroll
                for (int j2 = 0; j2 < 16; ++j2) {
                    float4 qa = qr[j2], ka = kr[j2];
                    acc = fmaf(qa.x, ka.x, acc);
                    acc = fmaf(qa.y, ka.y, acc);
                    acc = fmaf(qa.z, ka.z, acc);
                    acc = fmaf(qa.w, ka.w, acc);
                }
                if (acc > bE || (acc == bE && cI < bI)) { bE = acc; bI = cI; }
            }
        }
        #pragma unroll
        for (int off = 1; off < 4; off <<= 1) {
            float oE = __shfl_xor_sync(0xffffffffu, bE, off);
            int   oI = __shfl_xor_sync(0xffffffffu, bI, off);
            if (oE > bE || (oE == bE && oI < bI)) { bE = oE; bI = oI; }
        }
        if (bI == 0x7fffffff) bI = 0;
        if (tig == 0) attn[((size_t)b * NN + row) * NN + bI] = 1.0f;
        const float4* vs = reinterpret_cast<const float4*>(v + ((size_t)b * NN + bI) * DD);
        float4* dst = reinterpret_cast<float4*>(outp + ((size_t)b * NN + row) * DD);
        #pragma unroll
        for (int j2 = 0; j2 < 4; ++j2) dst[tig * 4 + j2] = vs[tig * 4 + j2];
    };
    finish(p0, r0);
    finish(p1, r1);
}

extern "C" void kernel_launch(void* const* d_in, const int* in_sizes, int n_in,
                              void* d_out, int out_size) {
    const float* q    = (const float*)d_in[0];
    const float* k    = (const float*)d_in[1];
    const float* v    = (const float*)d_in[2];
    const int*   mask = (const int*)d_in[3];

    float* attn = (float*)d_out;                   // [B, N, N]
    float* outp = attn + (size_t)BB * NN * NN;     // [B, N, D]

    dim3 grid(NN / TM, BB);
    attn_fused_kernel<<<grid, THREADS>>>(q, k, v, mask, attn, outp);
}

// round 12
// speedup vs baseline: 1.1674x; 1.1674x over previous
#include <cuda_runtime.h>
#include <cuda_bf16.h>
#include <cstdint>

constexpr int BB = 16, NN = 2048, DD = 64;
constexpr int TM = 128, TN = 128;
constexpr int THREADS = 256;          // 8 warps; warp w owns rows 16w..16w+15
constexpr int NT = NN / TN;           // 16 K-tiles
constexpr int KW = 36;                // K smem row stride in 4B words (72 bf16)

__device__ int g_argmax[BB * NN];     // per-row argmax (main -> scatter)

__device__ __forceinline__ uint32_t packbf(float x, float y) {
    __nv_bfloat162 h = __floats2bfloat162_rn(x, y);
    return *reinterpret_cast<uint32_t*>(&h);
}

__device__ __forceinline__ void mma16816(float* c, const uint32_t* a,
                                         uint32_t b0, uint32_t b1) {
    asm volatile(
        "mma.sync.aligned.m16n8k16.row.col.f32.bf16.bf16.f32 "
        "{%0,%1,%2,%3}, {%4,%5,%6,%7}, {%8,%9}, {%0,%1,%2,%3};"
        : "+f"(c[0]), "+f"(c[1]), "+f"(c[2]), "+f"(c[3])
        : "r"(a[0]), "r"(a[1]), "r"(a[2]), "r"(a[3]), "r"(b0), "r"(b1));
}

__device__ __forceinline__ void ldsm_x4(uint32_t& f0, uint32_t& f1,
                                        uint32_t& f2, uint32_t& f3, uint32_t addr) {
    asm volatile("ldmatrix.sync.aligned.m8n8.x4.shared.b16 {%0,%1,%2,%3}, [%4];"
                 : "=r"(f0), "=r"(f1), "=r"(f2), "=r"(f3) : "r"(addr));
}

constexpr unsigned NEGINF_BITS = 0xFF800000u;

// tile-local top-2 insert of packed (score|col); masked -> -inf falls through
__device__ __forceinline__ void ins2(float& A, float& B, float s, unsigned m, int col) {
    float pf = __int_as_float((__float_as_int(s) & 0xFFFFF800) | col);
    pf = m ? __int_as_float(NEGINF_BITS) : pf;
    float t = fminf(A, pf);
    A = fmaxf(A, pf);
    B = fmaxf(B, t);
}
__device__ __forceinline__ void ins4(float (&P)[4], float v) {
    float t1 = fminf(P[0], v); P[0] = fmaxf(P[0], v);
    float t2 = fminf(P[1], t1); P[1] = fmaxf(P[1], t1);
    float t3 = fminf(P[2], t2); P[2] = fmaxf(P[2], t2);
    P[3] = fmaxf(P[3], t3);
}

__global__ void __launch_bounds__(THREADS, 2)
attn_main_kernel(const float* __restrict__ q, const float* __restrict__ kmat,
                 const float* __restrict__ v, const int* __restrict__ maski,
                 float* __restrict__ outp)
{
    __shared__ __align__(16) uint32_t Ksm[TN * KW];        // 18 KB
    __shared__ __align__(16) uint8_t  smB[8][16][16];      // mask bits, 2 KB

    const int tid  = threadIdx.x;
    const int warp = tid >> 5;
    const int lane = tid & 31;
    const int g    = lane >> 2;
    const int tig  = lane & 3;
    const int b       = blockIdx.y;
    const int rowBase = blockIdx.x * TM;
    const int r0 = rowBase + warp * 16 + g;
    const int r1 = r0 + 8;

    uint32_t sKsm;
    asm("{ .reg .u64 t; cvta.to.shared.u64 t, %1; cvt.u32.u64 %0, t; }"
        : "=r"(sKsm) : "l"(Ksm));
    const int lm_m = lane >> 3;
    const int lm_r = lane & 7;
    const uint32_t lmBase = sKsm + 4u * ((uint32_t)(8 * (lm_m >> 1) + lm_r) * KW
                                         + (uint32_t)(lm_m & 1) * 4u);

    // ---- A fragments (Q rows r0,r1 as bf16), loaded once ----
    uint32_t aF[4][4];
    {
        const float* q0 = q + ((size_t)b * NN + r0) * DD;
        const float* q1 = q + ((size_t)b * NN + r1) * DD;
        #pragma unroll
        for (int s = 0; s < 4; ++s) {
            float2 x0 = *reinterpret_cast<const float2*>(q0 + 16 * s + 2 * tig);
            float2 x1 = *reinterpret_cast<const float2*>(q1 + 16 * s + 2 * tig);
            float2 x2 = *reinterpret_cast<const float2*>(q0 + 16 * s + 2 * tig + 8);
            float2 x3 = *reinterpret_cast<const float2*>(q1 + 16 * s + 2 * tig + 8);
            aF[s][0] = packbf(x0.x, x0.y);
            aF[s][1] = packbf(x1.x, x1.y);
            aF[s][2] = packbf(x2.x, x2.y);
            aF[s][3] = packbf(x3.x, x3.y);
        }
    }

    const float NEGINF = __int_as_float(NEGINF_BITS);
    float p0[4] = {NEGINF, NEGINF, NEGINF, NEGINF};
    float p1[4] = {NEGINF, NEGINF, NEGINF, NEGINF};

    // this warp's 16 mask rows, int4 view (NN/4 = 512 int4 per row)
    const int4* mwarp = reinterpret_cast<const int4*>(
        maski + ((size_t)b * NN + rowBase + warp * 16) * NN);
    const char* mwarpc = reinterpret_cast<const char*>(mwarp);

    for (int t = 0; t < NT; ++t) {
        if (t) __syncthreads();       // prior tile fully consumed

        // ---- prefetch next tile's mask lines into L2 (2 lines per lane) ----
        if (t + 1 < NT) {
            const char* p = mwarpc + (size_t)(lane >> 1) * (NN * 4)
                          + (t + 1) * (TN * 4) + (lane & 1) * 256;
            asm volatile("prefetch.global.L2 [%0];" :: "l"(p));
            asm volatile("prefetch.global.L2 [%0];" :: "l"(p + 128));
        }

        // ---- mask: coalesced load -> nibble pack -> shfl pair -> byte STS ----
        // batch (a,h): rows {2a,2a+1}, cols [64h, 64h+64) of this tile
        #pragma unroll
        for (int a = 0; a < 8; ++a) {
            #pragma unroll
            for (int h = 0; h < 2; ++h) {
                int4 m = __ldcs(mwarp + (size_t)(2 * a + (lane >> 4)) * (NN / 4)
                                + t * 32 + h * 16 + (lane & 15));
                uint32_t nib = (unsigned)(m.x != 0)        | ((unsigned)(m.y != 0) << 1)
                             | ((unsigned)(m.z != 0) << 2) | ((unsigned)(m.w != 0) << 3);
                uint32_t other = __shfl_down_sync(0xffffffffu, nib, 1);
                if (!(lane & 1))
                    smB[warp][2 * a + (lane >> 4)][8 * h + ((lane & 15) >> 1)] =
                        (uint8_t)(nib | (other << 4));
            }
        }

        // ---- K tile load + bf16 pack + STS ----
        {
            const float4* src = reinterpret_cast<const float4*>(
                kmat + ((size_t)b * NN + t * TN + (tid >> 1)) * DD) + (tid & 1) * 8;
            float4 f[8];
            #pragma unroll
            for (int i = 0; i < 8; ++i) f[i] = src[i];
            uint32_t* dst = Ksm + (tid >> 1) * KW + (tid & 1) * 16;
            #pragma unroll
            for (int qt = 0; qt < 4; ++qt)
                *reinterpret_cast<uint4*>(dst + qt * 4) =
                    make_uint4(packbf(f[2*qt].x,   f[2*qt].y),
                               packbf(f[2*qt].z,   f[2*qt].w),
                               packbf(f[2*qt+1].x, f[2*qt+1].y),
                               packbf(f[2*qt+1].z, f[2*qt+1].w));
        }
        __syncthreads();

        // ---- mask words for my two rows (linear bits: col c -> word c>>5) ----
        const uint4 W0 = *reinterpret_cast<const uint4*>(&smB[warp][g][0]);
        const uint4 W1 = *reinterpret_cast<const uint4*>(&smB[warp][8 + g][0]);
        const uint32_t w0a[4] = {W0.x, W0.y, W0.z, W0.w};
        const uint32_t w1a[4] = {W1.x, W1.y, W1.z, W1.w};

        float A0 = NEGINF, B0 = NEGINF, A1 = NEGINF, B1 = NEGINF;
        const int colBase = t * TN;

        #pragma unroll
        for (int jp = 0; jp < 8; ++jp) {
            float c2[2][4];
            #pragma unroll
            for (int u = 0; u < 2; ++u)
                #pragma unroll
                for (int e = 0; e < 4; ++e) c2[u][e] = 0.f;

            const uint32_t aj = lmBase + 4u * (uint32_t)((16 * jp) * KW);
            #pragma unroll
            for (int s = 0; s < 4; ++s) {
                uint32_t f0, f1, f2, f3;
                ldsm_x4(f0, f1, f2, f3, aj + 32u * s);
                mma16816(c2[0], aF[s], f0, f1);
                mma16816(c2[1], aF[s], f2, f3);
            }

            const uint32_t wa = w0a[jp >> 1] >> (16 * (jp & 1) + 2 * tig);
            const uint32_t wb = w1a[jp >> 1] >> (16 * (jp & 1) + 2 * tig);
            const int col0 = colBase + 16 * jp + 2 * tig;
            ins2(A0, B0, c2[0][0], wa & 1u,          col0);
            ins2(A0, B0, c2[0][1], wa & 2u,          col0 + 1);
            ins2(A1, B1, c2[0][2], wb & 1u,          col0);
            ins2(A1, B1, c2[0][3], wb & 2u,          col0 + 1);
            ins2(A0, B0, c2[1][0], (wa >> 8) & 1u,   col0 + 8);
            ins2(A0, B0, c2[1][1], (wa >> 8) & 2u,   col0 + 9);
            ins2(A1, B1, c2[1][2], (wb >> 8) & 1u,   col0 + 8);
            ins2(A1, B1, c2[1][3], (wb >> 8) & 2u,   col0 + 9);
        }

        ins4(p0, A0); ins4(p0, B0);
        ins4(p1, A1); ins4(p1, B1);
    }

    // ---- exact fp32 rescore of <=4 candidates/lane (round-2-verified order) ----
    auto finish = [&](float (&P)[4], int row) {
        float bE = -__int_as_float(0x7f800000);
        int   bI = 0x7fffffff;
        #pragma unroll
        for (int i = 0; i < 4; ++i) {
            if (P[i] != NEGINF) {
                const int cI = __float_as_int(P[i]) & 0x7FF;
                const float4* qr = reinterpret_cast<const float4*>(q + ((size_t)b * NN + row) * DD);
                const float4* kr = reinterpret_cast<const float4*>(kmat + ((size_t)b * NN + cI) * DD);
                float acc = 0.f;
                #pragma unroll
                for (int j2 = 0; j2 < 16; ++j2) {
                    float4 qa = qr[j2], ka = kr[j2];
                    acc = fmaf(qa.x, ka.x, acc);
                    acc = fmaf(qa.y, ka.y, acc);
                    acc = fmaf(qa.z, ka.z, acc);
                    acc = fmaf(qa.w, ka.w, acc);
                }
                if (acc > bE || (acc == bE && cI < bI)) { bE = acc; bI = cI; }
            }
        }
        #pragma unroll
        for (int off = 1; off < 4; off <<= 1) {
            float oE = __shfl_xor_sync(0xffffffffu, bE, off);
            int   oI = __shfl_xor_sync(0xffffffffu, bI, off);
            if (oE > bE || (oE == bE && oI < bI)) { bE = oE; bI = oI; }
        }
        if (bI == 0x7fffffff) bI = 0;
        if (tig == 0) g_argmax[b * NN + row] = bI;
        const float4* vs = reinterpret_cast<const float4*>(v + ((size_t)b * NN + bI) * DD);
        float4* dst = reinterpret_cast<float4*>(outp + ((size_t)b * NN + row) * DD);
        #pragma unroll
        for (int j2 = 0; j2 < 4; ++j2) dst[tig * 4 + j2] = vs[tig * 4 + j2];
    };
    finish(p0, r0);
    finish(p1, r1);
}

// scatter the single 1.0 per row (attn pre-zeroed by the overlapped memset)
__global__ void scatter_kernel(float* __restrict__ attn) {
    const int row = blockIdx.x * 256 + threadIdx.x;   // 0 .. BB*NN-1
    attn[(size_t)row * NN + g_argmax[row]] = 1.0f;
}

extern "C" void kernel_launch(void* const* d_in, const int* in_sizes, int n_in,
                              void* d_out, int out_size) {
    const float* q    = (const float*)d_in[0];
    const float* k    = (const float*)d_in[1];
    const float* v    = (const float*)d_in[2];
    const int*   mask = (const int*)d_in[3];

    float* attn = (float*)d_out;                   // [B, N, N]
    float* outp = attn + (size_t)BB * NN * NN;     // [B, N, D]

    static cudaStream_t s2 = nullptr;
    static cudaEvent_t  eFork = nullptr, eJoin = nullptr;
    if (!s2) {
        cudaStreamCreateWithFlags(&s2, cudaStreamNonBlocking);
        cudaEventCreateWithFlags(&eFork, cudaEventDisableTiming);
        cudaEventCreateWithFlags(&eJoin, cudaEventDisableTiming);
    }

    // fork: memset attn on s2, overlapped with the main compute kernel
    cudaEventRecord(eFork, 0);
    cudaStreamWaitEvent(s2, eFork, 0);
    cudaMemsetAsync(attn, 0, (size_t)BB * NN * NN * sizeof(float), s2);
    cudaEventRecord(eJoin, s2);

    dim3 grid(NN / TM, BB);
    attn_main_kernel<<<grid, THREADS>>>(q, k, v, mask, outp);

    // join: scatter needs both the memset and g_argmax
    cudaStreamWaitEvent(0, eJoin, 0);
    scatter_kernel<<<BB * NN / 256, 256>>>(attn);
}